// round 1
// baseline (speedup 1.0000x reference)
#include <cuda_runtime.h>
#include <math.h>

#define IMD   256
#define NPIX  65536       // 256*256
#define SSAMP 128
#define EXW_  256
#define EXH_  128
#define ENV_BSTRIDE (EXH_*EXW_*3)   // 98304 floats per batch
#define PI_F  3.14159265358979f

__device__ double g_loss;
__device__ double g_seg;

__global__ void zero_acc_kernel() {
    g_loss = 0.0;
    g_seg  = 0.0;
}

__device__ __forceinline__ float clamp01(float x) {
    return fminf(fmaxf(x, 0.0f), 1.0f);
}

// Branchless 3-float gather at element offset p (p = 3*pixelIndex).
// (pe + r) is always 8-byte aligned because (p + (p&1)) is even.
__device__ __forceinline__ float3 gather3(const float* __restrict__ base, int p) {
    const float* pe = base + p;
    int r = p & 1;
    float2 t = __ldg((const float2*)(pe + r));
    float  s = __ldg(pe + 2 - 2 * r);
    float3 o;
    o.x = r ? s   : t.x;
    o.y = r ? t.x : t.y;
    o.z = r ? t.y : s;
    return o;
}

__global__ __launch_bounds__(256) void render_kernel(
    const float* __restrict__ envx,   // (2,128,256,3)
    const float* __restrict__ envy,   // (2,128,256,3)
    const float* __restrict__ diffuse,// (3,256,256)
    const float* __restrict__ normal, // (3,256,256)
    const float* __restrict__ rough,  // (1,256,256)
    const float* __restrict__ seg,    // (256,256)
    const float* __restrict__ vmap,   // (3,256,256)
    const float* __restrict__ ls,     // (1,128,3)
    const float* __restrict__ ew,     // (1,128,1)
    const int*   __restrict__ idy,    // (128,256,256)
    const int*   __restrict__ idx,    // (128,256,256)
    float* __restrict__ out)          // [1 + 2*3*65536]
{
    __shared__ float s_ls[SSAMP * 3];
    __shared__ float s_ew[SSAMP];

    const int tid = threadIdx.x;
    for (int i = tid; i < SSAMP * 3; i += 256) s_ls[i] = ls[i];
    for (int i = tid; i < SSAMP;     i += 256) s_ew[i] = ew[i];
    __syncthreads();

    const int pix = blockIdx.x * 256 + tid;

    // ---- per-pixel constants ----
    const float nx = normal[pix], ny = normal[NPIX + pix], nz = normal[2 * NPIX + pix];
    const float vx = vmap[pix],   vy = vmap[NPIX + pix],   vz = vmap[2 * NPIX + pix];

    // camy = normalize(up - (up.n) n), up = (0,1,0)
    float cyx = -ny * nx;
    float cyy = 1.0f - ny * ny;
    float cyz = -ny * nz;
    {
        float cn  = sqrtf(cyx * cyx + cyy * cyy + cyz * cyz);
        float inv = 1.0f / fmaxf(cn, 1e-12f);
        cyx *= inv; cyy *= inv; cyz *= inv;
    }
    // cx = camy x n ; camx = -cx / ||cx||_1  (L1 normalization, as reference)
    float cxx = cyy * nz - cyz * ny;
    float cxy = cyz * nx - cyx * nz;
    float cxz = cyx * ny - cyy * nx;
    {
        float l1   = fabsf(cxx) + fabsf(cxy) + fabsf(cxz);
        float invl = -1.0f / fmaxf(l1, 1e-12f);
        cxx *= invl; cxy *= invl; cxz *= invl;
    }

    const float invTwoPi = 0.5f / PI_F;
    const float dB0 = (diffuse[pix]            + 1.0f) * invTwoPi;
    const float dB1 = (diffuse[NPIX + pix]     + 1.0f) * invTwoPi;
    const float dB2 = (diffuse[2 * NPIX + pix] + 1.0f) * invTwoPi;

    const float rB  = (rough[pix] + 1.0f) * 0.5f;
    const float kk  = (rB + 1.0f) * (rB + 1.0f) * 0.125f;
    float a2 = rB * rB; a2 = a2 * a2;
    const float omk  = 1.0f - kk;
    const float ndv  = clamp01(nx * vx + ny * vy + nz * vz);
    const float nom1 = ndv * omk + kk;
    const float a2m1 = a2 - 1.0f;

    const float* envx1 = envx + ENV_BSTRIDE;
    const float* envy1 = envy + ENV_BSTRIDE;

    float aX00 = 0.f, aX01 = 0.f, aX02 = 0.f;
    float aX10 = 0.f, aX11 = 0.f, aX12 = 0.f;
    float aY00 = 0.f, aY01 = 0.f, aY02 = 0.f;
    float aY10 = 0.f, aY11 = 0.f, aY12 = 0.f;

    #pragma unroll 2
    for (int s = 0; s < SSAMP; s++) {
        const int iy = __ldg(idy + s * NPIX + pix);
        const int ix = __ldg(idx + s * NPIX + pix);
        const int p  = (iy * EXW_ + ix) * 3;

        const float l0 = s_ls[3 * s + 0];
        const float l1 = s_ls[3 * s + 1];
        const float l2 = s_ls[3 * s + 2];

        // l = ls . basis
        const float lx = l0 * cxx + l1 * cyx + l2 * nx;
        const float ly = l0 * cxy + l1 * cyy + l2 * ny;
        const float lz = l0 * cxz + l1 * cyz + l2 * nz;

        // h = normalize((v + l)/2)  with clip(dot, 1e-6)
        float hx = (vx + lx) * 0.5f;
        float hy = (vy + ly) * 0.5f;
        float hz = (vz + lz) * 0.5f;
        const float hd   = hx * hx + hy * hy + hz * hz;
        const float hinv = rsqrtf(fmaxf(hd, 1e-6f));
        hx *= hinv; hy *= hinv; hz *= hinv;

        const float vdh   = vx * hx + vy * hy + vz * hz;
        const float frac0 = 0.05f + 0.95f * exp2f((-5.55472f * vdh - 6.98316f) * vdh);

        const float ndh = clamp01(nx * hx + ny * hy + nz * hz);
        const float ndl = clamp01(nx * lx + ny * ly + nz * lz);

        const float nom0 = ndh * ndh * a2m1 + 1.0f;
        const float nom2 = ndl * omk + kk;
        float nom = 4.0f * PI_F * nom0 * nom0 * nom1 * nom2;
        nom = fminf(fmaxf(nom, 1e-6f), 4.0f * PI_F);
        const float spec = __fdividef(a2 * frac0, nom);

        const float w  = s_ew[s];
        const float t  = ndl * w;
        const float u  = 10.0f * spec * t;
        const float c0 = dB0 * t + u;
        const float c1 = dB1 * t + u;
        const float c2 = dB2 * t + u;

        const float3 ex0 = gather3(envx,  p);
        const float3 ex1 = gather3(envx1, p);
        const float3 ey0 = gather3(envy,  p);
        const float3 ey1 = gather3(envy1, p);

        aX00 += c0 * ex0.x; aX01 += c1 * ex0.y; aX02 += c2 * ex0.z;
        aX10 += c0 * ex1.x; aX11 += c1 * ex1.y; aX12 += c2 * ex1.z;
        aY00 += c0 * ey0.x; aY01 += c1 * ey0.y; aY02 += c2 * ey0.z;
        aY10 += c0 * ey1.x; aY11 += c1 * ey1.y; aY12 += c2 * ey1.z;
    }

    // outputs: [0]=loss, [1 .. 1+3*NPIX) = pred[0], [1+3*NPIX .. ) = gt[0]
    out[1 + 0 * NPIX + pix] = aX00;
    out[1 + 1 * NPIX + pix] = aX01;
    out[1 + 2 * NPIX + pix] = aX02;
    out[1 + 3 * NPIX + 0 * NPIX + pix] = aY00;
    out[1 + 3 * NPIX + 1 * NPIX + pix] = aY01;
    out[1 + 3 * NPIX + 2 * NPIX + pix] = aY02;

    // loss contribution: sum over both batches, 3 channels
    float d;
    float lp = 0.0f;
    d = aX00 - aY00; lp += d * d;
    d = aX01 - aY01; lp += d * d;
    d = aX02 - aY02; lp += d * d;
    d = aX10 - aY10; lp += d * d;
    d = aX11 - aY11; lp += d * d;
    d = aX12 - aY12; lp += d * d;

    float sv = seg[pix];

    // warp reduce, then one double atomic per warp
    #pragma unroll
    for (int o = 16; o > 0; o >>= 1) {
        lp += __shfl_xor_sync(0xffffffffu, lp, o);
        sv += __shfl_xor_sync(0xffffffffu, sv, o);
    }
    if ((tid & 31) == 0) {
        atomicAdd(&g_loss, (double)lp);
        atomicAdd(&g_seg,  (double)sv);
    }
}

__global__ void finalize_kernel(float* __restrict__ out) {
    // pixel_num = seg.sum() * B * 3 = segsum * 6
    out[0] = (float)(g_loss / (g_seg * 6.0));
}

extern "C" void kernel_launch(void* const* d_in, const int* in_sizes, int n_in,
                              void* d_out, int out_size) {
    const float* x       = (const float*)d_in[0];
    const float* y       = (const float*)d_in[1];
    const float* diffuse = (const float*)d_in[2];
    const float* normal  = (const float*)d_in[3];
    const float* rough   = (const float*)d_in[4];
    const float* seg     = (const float*)d_in[5];
    const float* v       = (const float*)d_in[6];
    const float* ls      = (const float*)d_in[7];
    const float* ew      = (const float*)d_in[8];
    const int*   idy     = (const int*)d_in[9];
    const int*   idx     = (const int*)d_in[10];
    float* out = (float*)d_out;

    zero_acc_kernel<<<1, 1>>>();
    render_kernel<<<NPIX / 256, 256>>>(x, y, diffuse, normal, rough, seg, v,
                                       ls, ew, idy, idx, out);
    finalize_kernel<<<1, 1>>>(out);
}